// round 14
// baseline (speedup 1.0000x reference)
#include <cuda_runtime.h>
#include <cstdint>

#define TOK    16384
#define DIM    2048
#define NE     16
#define BT     128
#define NTHR   512
#define NCHUNK 32

// smem: A stages [0, 65536): s*32768 + (hi 16384 | lo 16384); W blob [65536, 196608)
#define WB 65536u
#define SMEM_BYTES (65536 + 131072 + 1024)   // +1KB slack = 197632

__device__ __forceinline__ uint32_t smem_u32(const void* p) {
    uint32_t a;
    asm("{ .reg .u64 t; cvta.to.shared.u64 t, %1; cvt.u32.u64 %0, t; }" : "=r"(a) : "l"(p));
    return a;
}

#define STS128(addr, r0, r1, r2, r3) \
    asm volatile("st.shared.v4.b32 [%0], {%1,%2,%3,%4};" \
        :: "r"(addr), "r"(r0), "r"(r1), "r"(r2), "r"(r3) : "memory")
#define STS32U(addr, v) asm volatile("st.shared.b32 [%0], %1;" :: "r"(addr), "r"(v) : "memory")
#define STS64(addr, a, b) \
    asm volatile("st.shared.v2.f32 [%0], {%1, %2};" :: "r"(addr), "f"(a), "f"(b) : "memory")
#define LDS32F(v, addr) asm volatile("ld.shared.f32 %0, [%1];" : "=f"(v) : "r"(addr))
#define LDS32U(v, addr) asm volatile("ld.shared.b32 %0, [%1];" : "=r"(v) : "r"(addr))

#define LDMX4(r0, r1, r2, r3, addr) \
    asm volatile("ldmatrix.sync.aligned.m8n8.x4.shared.b16 {%0,%1,%2,%3}, [%4];" \
        : "=r"(r0), "=r"(r1), "=r"(r2), "=r"(r3) : "r"(addr))

#define MMA_BF16(d, a0, a1, a2, a3, b0, b1)                                \
    asm volatile("mma.sync.aligned.m16n8k16.row.col.f32.bf16.bf16.f32 "    \
        "{%0,%1,%2,%3},{%4,%5,%6,%7},{%8,%9},{%0,%1,%2,%3};"               \
        : "+f"(d[0]), "+f"(d[1]), "+f"(d[2]), "+f"(d[3])                   \
        : "r"(a0), "r"(a1), "r"(a2), "r"(a3), "r"(b0), "r"(b1))

// f32 pair -> packed bf16x2 hi (truncation; low half = f0) + bf16x2 lo (rounded residual)
__device__ __forceinline__ void cvt_pair(float f0, float f1, uint32_t& hi, uint32_t& lo) {
    uint32_t u0 = __float_as_uint(f0) & 0xffff0000u;
    uint32_t u1 = __float_as_uint(f1) & 0xffff0000u;
    asm("prmt.b32 %0, %1, %2, 0x7632;" : "=r"(hi) : "r"(u0), "r"(u1));
    float l0 = f0 - __uint_as_float(u0);
    float l1 = f1 - __uint_as_float(u1);
    asm("cvt.rn.bf16x2.f32 %0, %1, %2;" : "=r"(lo) : "f"(l1), "f"(l0));  // upper=l1, lower=l0
}

__global__ void __launch_bounds__(NTHR, 1)
gating_moe_kernel(const float* __restrict__ x,
                  const float* __restrict__ noise,
                  const float* __restrict__ W,
                  const float* __restrict__ b,
                  float* __restrict__ out)
{
    extern __shared__ float sm[];
    const uint32_t sb = smem_u32(sm);
    const int tid  = threadIdx.x;
    const int l    = tid & 31;
    const int w    = tid >> 5;
    const int tgw  = w & 7;          // token group (16 tokens)
    const int et   = w >> 3;         // expert tile (8 experts)
    const int tok0 = blockIdx.x * BT;

    // ---- one-time W split into the blob: [kg 0..127][et 0..1] x 512 B ----
    // 512 B = 4 tiles x 128 B (hi k0-7 | hi k8-15 | lo k0-7 | lo k8-15),
    // tile: row = expert (0..7), 16 B per row; u32 = k-pair
    #pragma unroll
    for (int k = 0; k < 32; k++) {
        int idx = tid + NTHR * k;            // k-pair index, 16384 total
        int e   = idx >> 10;                 // expert 0..15
        int pd  = idx & 1023;                // global k-pair 0..1023
        float2 wv = *(const float2*)(W + (size_t)e * DIM + 2 * pd);
        uint32_t h, lo;
        cvt_pair(wv.x, wv.y, h, lo);
        int kgg = pd >> 3;                   // k16-group 0..127
        int p   = pd & 7;                    // pair within group
        uint32_t base = WB + (uint32_t)(kgg * 1024 + (e >> 3) * 512);
        uint32_t off  = (uint32_t)((p >> 2) * 128 + (e & 7) * 16 + (p & 3) * 4);
        STS32U(sb + base + off, h);
        STS32U(sb + base + off + 256u, lo);
    }

    // ---- producer mapping: thread -> (token row, 16-dim slice pj) ----
    const int prow = tid >> 2;
    const int pj   = tid & 3;
    const float4* xp4 = (const float4*)(x + (size_t)(tok0 + prow) * DIM + pj * 16);
    const uint32_t o0   = (uint32_t)(prow * 128 + pj * 32);
    const uint32_t sts1 = o0 ^ ((o0 >> 3) & 0x70u);
    const uint32_t sts2 = sts1 ^ 16u;        // sw(o0+16) == sw(o0) XOR 16 (NOT +16)

    // ---- consumer geometry ----
    const uint32_t rowterm = (uint32_t)((tgw * 16 + (l & 15)) * 128 + ((l >> 4) << 4));
    const uint32_t lanB    = (uint32_t)(et * 512 + (l >> 2) * 16 + (l & 3) * 4);

    float d[4] = {0.f, 0.f, 0.f, 0.f};
    float4 xv0, xv1, xv2, xv3;

    // produce chunk 0 into stage 0
    xv0 = xp4[0]; xv1 = xp4[1]; xv2 = xp4[2]; xv3 = xp4[3];
    {
        const uint32_t hb = sb;
        uint32_t h0, h1, h2, h3, l0, l1, l2, l3;
        cvt_pair(xv0.x, xv0.y, h0, l0); cvt_pair(xv0.z, xv0.w, h1, l1);
        cvt_pair(xv1.x, xv1.y, h2, l2); cvt_pair(xv1.z, xv1.w, h3, l3);
        STS128(hb + sts1, h0, h1, h2, h3);
        STS128(hb + 16384u + sts1, l0, l1, l2, l3);
        cvt_pair(xv2.x, xv2.y, h0, l0); cvt_pair(xv2.z, xv2.w, h1, l1);
        cvt_pair(xv3.x, xv3.y, h2, l2); cvt_pair(xv3.z, xv3.w, h3, l3);
        STS128(hb + sts2, h0, h1, h2, h3);
        STS128(hb + 16384u + sts2, l0, l1, l2, l3);
    }
    __syncthreads();

    for (int c = 0; c < NCHUNK; c++) {
        if (c + 1 < NCHUNK) {
            xv0 = xp4[(c + 1) * 16];     xv1 = xp4[(c + 1) * 16 + 1];
            xv2 = xp4[(c + 1) * 16 + 2]; xv3 = xp4[(c + 1) * 16 + 3];
        }

        // ---- consume stage c&1 ----
        const uint32_t ab = sb + (uint32_t)(c & 1) * 32768u;
        #pragma unroll
        for (int kg = 0; kg < 4; kg++) {
            uint32_t lg = rowterm + (uint32_t)(kg * 32);
            uint32_t sw = lg ^ ((lg >> 3) & 0x70u);
            uint32_t ah0, ah1, ah2, ah3, al0, al1, al2, al3;
            LDMX4(ah0, ah1, ah2, ah3, ab + sw);
            LDMX4(al0, al1, al2, al3, ab + 16384u + sw);

            // B fragments via conflict-free LDS32
            const uint32_t kb = sb + WB + (uint32_t)((c * 4 + kg) * 1024) + lanB;
            uint32_t bh0, bh1, bl0, bl1;
            LDS32U(bh0, kb);
            LDS32U(bh1, kb + 128u);
            LDS32U(bl0, kb + 256u);
            LDS32U(bl1, kb + 384u);

            MMA_BF16(d, ah0, ah1, ah2, ah3, bh0, bh1);
            MMA_BF16(d, ah0, ah1, ah2, ah3, bl0, bl1);
            MMA_BF16(d, al0, al1, al2, al3, bh0, bh1);
        }

        // ---- produce chunk c+1 into the other stage ----
        if (c + 1 < NCHUNK) {
            const uint32_t hb = sb + (uint32_t)((c + 1) & 1) * 32768u;
            uint32_t h0, h1, h2, h3, l0, l1, l2, l3;
            cvt_pair(xv0.x, xv0.y, h0, l0); cvt_pair(xv0.z, xv0.w, h1, l1);
            cvt_pair(xv1.x, xv1.y, h2, l2); cvt_pair(xv1.z, xv1.w, h3, l3);
            STS128(hb + sts1, h0, h1, h2, h3);
            STS128(hb + 16384u + sts1, l0, l1, l2, l3);
            cvt_pair(xv2.x, xv2.y, h0, l0); cvt_pair(xv2.z, xv2.w, h1, l1);
            cvt_pair(xv3.x, xv3.y, h2, l2); cvt_pair(xv3.z, xv3.w, h3, l3);
            STS128(hb + sts2, h0, h1, h2, h3);
            STS128(hb + 16384u + sts2, l0, l1, l2, l3);
        }
        __syncthreads();
    }

    // ---- logits to smem (reuse stage 0), pitch 18 ----
    const uint32_t lb = sb;
    {
        const int g = l >> 2, tg4 = l & 3;
        const int rA = tgw * 16 + g, rB = rA + 8, cb = et * 8 + 2 * tg4;
        STS64(lb + (uint32_t)(rA * 18 + cb) * 4u, d[0], d[1]);
        STS64(lb + (uint32_t)(rB * 18 + cb) * 4u, d[2], d[3]);
    }
    __syncthreads();

    // ---- epilogue: one token per thread (threads 0..127) ----
    if (tid < BT) {
        const int gtok = tok0 + tid;
        const float4* nz = (const float4*)(noise + (size_t)gtok * NE);
        float4 n0 = nz[0], n1 = nz[1], n2 = nz[2], n3 = nz[3];
        const float4* bb4 = (const float4*)b;
        float4 q0 = bb4[0], q1 = bb4[1], q2 = bb4[2], q3 = bb4[3];

        float nn[16] = {n0.x, n0.y, n0.z, n0.w, n1.x, n1.y, n1.z, n1.w,
                        n2.x, n2.y, n2.z, n2.w, n3.x, n3.y, n3.z, n3.w};
        float bv[16] = {q0.x, q0.y, q0.z, q0.w, q1.x, q1.y, q1.z, q1.w,
                        q2.x, q2.y, q2.z, q2.w, q3.x, q3.y, q3.z, q3.w};

        float v[16];
        #pragma unroll
        for (int e = 0; e < 16; e++) {
            float lg;
            LDS32F(lg, lb + (uint32_t)(tid * 18 + e) * 4u);
            v[e] = lg + bv[e] + 0.1f * nn[e];
        }

        // top-2 (stable: earlier index wins ties, matching jax top_k)
        float v1 = -1e30f, v2 = -1e30f;
        int   i1 = -1,     i2 = -1;
        #pragma unroll
        for (int e = 0; e < 16; e++) {
            float val = v[e];
            if (val > v1)      { v2 = v1; i2 = i1; v1 = val; i1 = e; }
            else if (val > v2) { v2 = val; i2 = e; }
        }

        float ew  = expf(v2 - v1);
        float inv = 1.0f / (1.0f + ew);
        float w1  = inv;
        float w2  = ew * inv;

        float o[16];
        #pragma unroll
        for (int e = 0; e < 16; e++)
            o[e] = (e == i1) ? w1 : ((e == i2) ? w2 : 0.0f);

        float4* op = (float4*)(out + (size_t)gtok * NE);
        op[0] = make_float4(o[0],  o[1],  o[2],  o[3]);
        op[1] = make_float4(o[4],  o[5],  o[6],  o[7]);
        op[2] = make_float4(o[8],  o[9],  o[10], o[11]);
        op[3] = make_float4(o[12], o[13], o[14], o[15]);
    }
}

extern "C" void kernel_launch(void* const* d_in, const int* in_sizes, int n_in,
                              void* d_out, int out_size)
{
    const float* x     = (const float*)d_in[0];
    const float* noise = (const float*)d_in[1];
    const float* W     = (const float*)d_in[2];
    const float* b     = (const float*)d_in[3];
    float* out = (float*)d_out;

    cudaFuncSetAttribute(gating_moe_kernel,
                         cudaFuncAttributeMaxDynamicSharedMemorySize, SMEM_BYTES);
    gating_moe_kernel<<<TOK / BT, NTHR, SMEM_BYTES>>>(x, noise, W, b, out);
}

// round 15
// speedup vs baseline: 1.2069x; 1.2069x over previous
#include <cuda_runtime.h>
#include <cstdint>

#define TOK    16384
#define DIM    2048
#define NE     16
#define BT     128
#define NTHR   512
#define NCHUNK 32

// smem: A stages [0, 65536): s*32768 + (hi 16384 | lo 16384); W blob [65536, 196608)
#define WB 65536u
#define SMEM_BYTES (65536 + 131072 + 1024)   // 197632

__device__ __forceinline__ uint32_t smem_u32(const void* p) {
    uint32_t a;
    asm("{ .reg .u64 t; cvta.to.shared.u64 t, %1; cvt.u32.u64 %0, t; }" : "=r"(a) : "l"(p));
    return a;
}

#define STS32U(addr, v) asm volatile("st.shared.b32 [%0], %1;" :: "r"(addr), "r"(v) : "memory")
#define STS64U(addr, a, b) \
    asm volatile("st.shared.v2.b32 [%0], {%1, %2};" :: "r"(addr), "r"(a), "r"(b) : "memory")
#define STS64F(addr, a, b) \
    asm volatile("st.shared.v2.f32 [%0], {%1, %2};" :: "r"(addr), "f"(a), "f"(b) : "memory")
#define LDS32F(v, addr) asm volatile("ld.shared.f32 %0, [%1];" : "=f"(v) : "r"(addr))
#define LDS32U(v, addr) asm volatile("ld.shared.b32 %0, [%1];" : "=r"(v) : "r"(addr))

#define LDMX4(r0, r1, r2, r3, addr) \
    asm volatile("ldmatrix.sync.aligned.m8n8.x4.shared.b16 {%0,%1,%2,%3}, [%4];" \
        : "=r"(r0), "=r"(r1), "=r"(r2), "=r"(r3) : "r"(addr))

#define MMA_BF16(d, a0, a1, a2, a3, b0, b1)                                \
    asm volatile("mma.sync.aligned.m16n8k16.row.col.f32.bf16.bf16.f32 "    \
        "{%0,%1,%2,%3},{%4,%5,%6,%7},{%8,%9},{%0,%1,%2,%3};"               \
        : "+f"(d[0]), "+f"(d[1]), "+f"(d[2]), "+f"(d[3])                   \
        : "r"(a0), "r"(a1), "r"(a2), "r"(a3), "r"(b0), "r"(b1))

// f32 pair -> packed bf16x2 hi (truncation; low half = f0) + bf16x2 lo (rounded residual)
__device__ __forceinline__ void cvt_pair(float f0, float f1, uint32_t& hi, uint32_t& lo) {
    uint32_t u0 = __float_as_uint(f0) & 0xffff0000u;
    uint32_t u1 = __float_as_uint(f1) & 0xffff0000u;
    asm("prmt.b32 %0, %1, %2, 0x7632;" : "=r"(hi) : "r"(u0), "r"(u1));
    float l0 = f0 - __uint_as_float(u0);
    float l1 = f1 - __uint_as_float(u1);
    asm("cvt.rn.bf16x2.f32 %0, %1, %2;" : "=r"(lo) : "f"(l1), "f"(l0));
}

__global__ void __launch_bounds__(NTHR, 1)
gating_moe_kernel(const float* __restrict__ x,
                  const float* __restrict__ noise,
                  const float* __restrict__ W,
                  const float* __restrict__ b,
                  float* __restrict__ out)
{
    extern __shared__ float sm[];
    const uint32_t sb = smem_u32(sm);
    const int tid  = threadIdx.x;
    const int l    = tid & 31;
    const int w    = tid >> 5;
    const int tgw  = w & 7;          // token group (16 tokens)
    const int kh   = w >> 3;         // k-half of each chunk (kg 0-1 / 2-3)
    const int tok0 = blockIdx.x * BT;

    // ---- one-time W split blob: [kg 0..127] x 1024 B; per kg: et0 512 | et1 512;
    //      per et: hi k0-7 (128) | hi k8-15 | lo k0-7 | lo k8-15; row=expert, u32=k-pair
    #pragma unroll
    for (int k = 0; k < 32; k++) {
        int idx = tid + NTHR * k;
        int e   = idx >> 10;
        int pd  = idx & 1023;
        float2 wv = *(const float2*)(W + (size_t)e * DIM + 2 * pd);
        uint32_t h, lo;
        cvt_pair(wv.x, wv.y, h, lo);
        int kgg = pd >> 3;
        int p   = pd & 7;
        uint32_t base = WB + (uint32_t)(kgg * 1024 + (e >> 3) * 512);
        uint32_t off  = (uint32_t)((p >> 2) * 128 + (e & 7) * 16 + (p & 3) * 4);
        STS32U(sb + base + off, h);
        STS32U(sb + base + off + 256u, lo);
    }

    // ---- coalesced producer: u-th load = float4 at idx = tid + 512u ----
    // row_u = (tid>>4) + 32u, slice = tid&15 (8 bytes bf16 per slice)
    const int r0q = tid >> 4;
    const int sl  = tid & 15;
    const float* xg = x + (size_t)(tok0 + r0q) * DIM + sl * 4;   // + u*32*DIM + c*64
    uint32_t stsH[4];
    #pragma unroll
    for (int u = 0; u < 4; u++) {
        uint32_t o = (uint32_t)(((r0q + 32 * u) * 128) + sl * 8);
        stsH[u] = o ^ ((o >> 3) & 0x70u);
    }

    // ---- consumer geometry ----
    const uint32_t rowterm = (uint32_t)((tgw * 16 + (l & 15)) * 128 + ((l >> 4) << 4));
    const uint32_t lanB    = (uint32_t)((l >> 2) * 16 + (l & 3) * 4);

    float d0[4] = {0.f, 0.f, 0.f, 0.f};   // experts 0-7
    float d1[4] = {0.f, 0.f, 0.f, 0.f};   // experts 8-15
    float4 xv[4];

    // produce chunk 0 into stage 0
    #pragma unroll
    for (int u = 0; u < 4; u++) xv[u] = *(const float4*)(xg + u * 32 * DIM);
    {
        const uint32_t hb = sb;
        #pragma unroll
        for (int u = 0; u < 4; u++) {
            uint32_t h0, h1, l0, l1;
            cvt_pair(xv[u].x, xv[u].y, h0, l0);
            cvt_pair(xv[u].z, xv[u].w, h1, l1);
            STS64U(hb + stsH[u], h0, h1);
            STS64U(hb + 16384u + stsH[u], l0, l1);
        }
    }
    __syncthreads();

    for (int c = 0; c < NCHUNK; c++) {
        if (c + 1 < NCHUNK) {
            #pragma unroll
            for (int u = 0; u < 4; u++)
                xv[u] = *(const float4*)(xg + (c + 1) * 64 + u * 32 * DIM);
        }

        // ---- consume stage c&1: this warp's k-half (kg = kh*2, kh*2+1) ----
        const uint32_t ab = sb + (uint32_t)(c & 1) * 32768u;
        #pragma unroll
        for (int kgl = 0; kgl < 2; kgl++) {
            const int kg = kh * 2 + kgl;
            uint32_t lg = rowterm + (uint32_t)(kg * 32);
            uint32_t sw = lg ^ ((lg >> 3) & 0x70u);
            uint32_t ah0, ah1, ah2, ah3, al0, al1, al2, al3;
            LDMX4(ah0, ah1, ah2, ah3, ab + sw);
            LDMX4(al0, al1, al2, al3, ab + 16384u + sw);

            const uint32_t kb = sb + WB + (uint32_t)((c * 4 + kg) * 1024) + lanB;
            uint32_t b0h0, b0h1, b0l0, b0l1, b1h0, b1h1, b1l0, b1l1;
            LDS32U(b0h0, kb);           LDS32U(b0h1, kb + 128u);
            LDS32U(b0l0, kb + 256u);    LDS32U(b0l1, kb + 384u);
            LDS32U(b1h0, kb + 512u);    LDS32U(b1h1, kb + 640u);
            LDS32U(b1l0, kb + 768u);    LDS32U(b1l1, kb + 896u);

            MMA_BF16(d0, ah0, ah1, ah2, ah3, b0h0, b0h1);
            MMA_BF16(d0, ah0, ah1, ah2, ah3, b0l0, b0l1);
            MMA_BF16(d0, al0, al1, al2, al3, b0h0, b0h1);
            MMA_BF16(d1, ah0, ah1, ah2, ah3, b1h0, b1h1);
            MMA_BF16(d1, ah0, ah1, ah2, ah3, b1l0, b1l1);
            MMA_BF16(d1, al0, al1, al2, al3, b1h0, b1h1);
        }

        // ---- produce chunk c+1 into the other stage ----
        if (c + 1 < NCHUNK) {
            const uint32_t hb = sb + (uint32_t)((c + 1) & 1) * 32768u;
            #pragma unroll
            for (int u = 0; u < 4; u++) {
                uint32_t h0, h1, l0, l1;
                cvt_pair(xv[u].x, xv[u].y, h0, l0);
                cvt_pair(xv[u].z, xv[u].w, h1, l1);
                STS64U(hb + stsH[u], h0, h1);
                STS64U(hb + 16384u + stsH[u], l0, l1);
            }
        }
        __syncthreads();
    }

    // ---- k-half partials -> two [128][18] buffers (reuse stage area) ----
    {
        const uint32_t lb = sb + (uint32_t)kh * 9216u;
        const int rA = tgw * 16 + (l >> 2);
        const int rB = rA + 8;
        const int cb = 2 * (l & 3);
        STS64F(lb + (uint32_t)(rA * 18 + cb) * 4u,     d0[0], d0[1]);
        STS64F(lb + (uint32_t)(rB * 18 + cb) * 4u,     d0[2], d0[3]);
        STS64F(lb + (uint32_t)(rA * 18 + 8 + cb) * 4u, d1[0], d1[1]);
        STS64F(lb + (uint32_t)(rB * 18 + 8 + cb) * 4u, d1[2], d1[3]);
    }
    __syncthreads();

    // ---- epilogue: one token per thread (threads 0..127) ----
    if (tid < BT) {
        const int gtok = tok0 + tid;
        const float4* nz = (const float4*)(noise + (size_t)gtok * NE);
        float4 n0 = nz[0], n1 = nz[1], n2 = nz[2], n3 = nz[3];
        const float4* bb4 = (const float4*)b;
        float4 q0 = bb4[0], q1 = bb4[1], q2 = bb4[2], q3 = bb4[3];

        float nn[16] = {n0.x, n0.y, n0.z, n0.w, n1.x, n1.y, n1.z, n1.w,
                        n2.x, n2.y, n2.z, n2.w, n3.x, n3.y, n3.z, n3.w};
        float bv[16] = {q0.x, q0.y, q0.z, q0.w, q1.x, q1.y, q1.z, q1.w,
                        q2.x, q2.y, q2.z, q2.w, q3.x, q3.y, q3.z, q3.w};

        float v[16];
        #pragma unroll
        for (int e = 0; e < 16; e++) {
            float l0, l1;
            LDS32F(l0, sb + (uint32_t)(tid * 18 + e) * 4u);
            LDS32F(l1, sb + 9216u + (uint32_t)(tid * 18 + e) * 4u);
            v[e] = (l0 + l1) + bv[e] + 0.1f * nn[e];
        }

        // top-2 (stable: earlier index wins ties, matching jax top_k)
        float v1 = -1e30f, v2 = -1e30f;
        int   i1 = -1,     i2 = -1;
        #pragma unroll
        for (int e = 0; e < 16; e++) {
            float val = v[e];
            if (val > v1)      { v2 = v1; i2 = i1; v1 = val; i1 = e; }
            else if (val > v2) { v2 = val; i2 = e; }
        }

        float ew  = expf(v2 - v1);
        float inv = 1.0f / (1.0f + ew);
        float w1  = inv;
        float w2  = ew * inv;

        float o[16];
        #pragma unroll
        for (int e = 0; e < 16; e++)
            o[e] = (e == i1) ? w1 : ((e == i2) ? w2 : 0.0f);

        float4* op = (float4*)(out + (size_t)gtok * NE);
        op[0] = make_float4(o[0],  o[1],  o[2],  o[3]);
        op[1] = make_float4(o[4],  o[5],  o[6],  o[7]);
        op[2] = make_float4(o[8],  o[9],  o[10], o[11]);
        op[3] = make_float4(o[12], o[13], o[14], o[15]);
    }
}

extern "C" void kernel_launch(void* const* d_in, const int* in_sizes, int n_in,
                              void* d_out, int out_size)
{
    const float* x     = (const float*)d_in[0];
    const float* noise = (const float*)d_in[1];
    const float* W     = (const float*)d_in[2];
    const float* b     = (const float*)d_in[3];
    float* out = (float*)d_out;

    cudaFuncSetAttribute(gating_moe_kernel,
                         cudaFuncAttributeMaxDynamicSharedMemorySize, SMEM_BYTES);
    gating_moe_kernel<<<TOK / BT, NTHR, SMEM_BYTES>>>(x, noise, W, b, out);
}